// round 13
// baseline (speedup 1.0000x reference)
#include <cuda_runtime.h>
#include <cuda_bf16.h>
#include <math.h>
#include <stdint.h>

#define S   8192
#define H2  1024
#define AA  2048
#define NT  16       // N-tiles of 128 per head
#define KTC 96       // K'-chunks of 32 (3-term folded K)
#define KST 64       // stored chunks per operand (hi|lo)
#define MT  64       // M-tiles of 128
#define NCHUNK 128   // output chunks of 64 rows
#define STG 32768    // bytes per pipeline stage (A 16KB + B 16KB)
#define RED_OFF (3 * STG)
#define GSMEM   (RED_OFF + 2048)

// A tiles: [mt][64][128 rows][32 halves] (8KB/chunk, SW64 rows of 64B)  = 32MB
// B tiles: [head*16+nt][64][2 sub][32 k][64 n halves] (8KB/chunk, SW128) = 24MB
__device__ char  g_Abf[(size_t)MT * KST * 8192];
__device__ char  g_Bbf[(size_t)3 * NT * KST * 8192];
__device__ float g_cb[3 * AA];
__device__ float g_epart[(size_t)3 * NT * S];
__device__ float g_efull[3 * S];
__device__ float g_fused[S];
__device__ float g_outpart[NCHUNK * H2];

// ---------------- helpers ----------------
__device__ __forceinline__ uint32_t smem_u32(const void* p) {
    uint32_t a;
    asm("{ .reg .u64 t; cvta.to.shared.u64 t, %1; cvt.u32.u64 %0, t; }" : "=r"(a) : "l"(p));
    return a;
}
__device__ __forceinline__ uint32_t sw64(uint32_t x)  { return x ^ ((x >> 3) & 0x30); }
__device__ __forceinline__ uint32_t sw128(uint32_t x) { return x ^ ((x >> 3) & 0x70); }

__device__ __forceinline__ void cp16(uint32_t saddr, const void* gaddr) {
    asm volatile("cp.async.cg.shared.global [%0], [%1], 16;" :: "r"(saddr), "l"(gaddr));
}
__device__ __forceinline__ void cp_commit() { asm volatile("cp.async.commit_group;"); }
__device__ __forceinline__ void cp_wait1()  { asm volatile("cp.async.wait_group 1;"); }
__device__ __forceinline__ void cp_wait0()  { asm volatile("cp.async.wait_group 0;"); }

__device__ __forceinline__ void ldsm4(uint32_t* r, uint32_t addr) {
    asm volatile("ldmatrix.sync.aligned.m8n8.x4.shared.b16 {%0,%1,%2,%3}, [%4];"
                 : "=r"(r[0]), "=r"(r[1]), "=r"(r[2]), "=r"(r[3]) : "r"(addr));
}
__device__ __forceinline__ void ldsm4t(uint32_t* r, uint32_t addr) {
    asm volatile("ldmatrix.sync.aligned.m8n8.x4.trans.shared.b16 {%0,%1,%2,%3}, [%4];"
                 : "=r"(r[0]), "=r"(r[1]), "=r"(r[2]), "=r"(r[3]) : "r"(addr));
}
__device__ __forceinline__ void mma16816(float* d, const uint32_t* a, uint32_t b0, uint32_t b1) {
    asm volatile(
        "mma.sync.aligned.m16n8k16.row.col.f32.bf16.bf16.f32 "
        "{%0,%1,%2,%3}, {%4,%5,%6,%7}, {%8,%9}, {%0,%1,%2,%3};"
        : "+f"(d[0]), "+f"(d[1]), "+f"(d[2]), "+f"(d[3])
        : "r"(a[0]), "r"(a[1]), "r"(a[2]), "r"(a[3]), "r"(b0), "r"(b1));
}
__device__ __forceinline__ float tanha(float x) {
    float y;
    asm("tanh.approx.f32 %0, %1;" : "=f"(y) : "f"(x));
    return y;
}

// ---------------- conv A: fp32 sentence -> bf16 hi|lo swizzled tiles ---------
__global__ void convA_kernel(const float* __restrict__ sent, const int* __restrict__ lenp)
{
    int len = *lenp; if (len > S) len = S;
    int mlim = (len + 127) & ~127;
    int idx = blockIdx.x * 256 + threadIdx.x;
    int m = idx >> 10;
    if (m >= mlim) return;
    int k = idx & 1023;
    float x = sent[idx];
    __nv_bfloat16 hi = __float2bfloat16(x);
    __nv_bfloat16 lo = __float2bfloat16(x - __bfloat162float(hi));
    int mt = m >> 7, r = m & 127, kc = k >> 5, c = k & 31;
    uint32_t off = sw64((uint32_t)(r * 64 + c * 2));
    char* base = g_Abf + (size_t)mt * KST * 8192;
    *(__nv_bfloat16*)(base + (size_t)kc * 8192 + off)        = hi;
    *(__nv_bfloat16*)(base + (size_t)(32 + kc) * 8192 + off) = lo;
}

// ---------------- conv B: W[k][n] -> bf16 hi|lo swizzled [k][n] tiles --------
__global__ void convB_kernel(const float* __restrict__ W0, const float* __restrict__ W1,
                             const float* __restrict__ W2)
{
    int idx = blockIdx.x * 256 + threadIdx.x;
    int head = idx >> 21;
    int rem = idx & ((1 << 21) - 1);
    int k = rem >> 11, n = rem & 2047;
    const float* W = (head == 0) ? W0 : (head == 1) ? W1 : W2;
    float x = W[rem];
    __nv_bfloat16 hi = __float2bfloat16(x);
    __nv_bfloat16 lo = __float2bfloat16(x - __bfloat162float(hi));
    int nt = n >> 7, nloc = n & 127, sub = nloc >> 6, nc = nloc & 63;
    int kc = k >> 5, kr = k & 31;
    uint32_t off = (uint32_t)(sub * 4096) + sw128((uint32_t)(kr * 128 + nc * 2));
    char* base = g_Bbf + (size_t)(head * NT + nt) * KST * 8192;
    *(__nv_bfloat16*)(base + (size_t)kc * 8192 + off)        = hi;
    *(__nv_bfloat16*)(base + (size_t)(32 + kc) * 8192 + off) = lo;
}

// ---------------- context bias: cb = b_s + b_c + ctx @ W_c -------------------
__global__ void cb_kernel(const float* __restrict__ ctx0, const float* __restrict__ ctx1,
                          const float* __restrict__ ctx2,
                          const float* __restrict__ Wc0, const float* __restrict__ Wc1,
                          const float* __restrict__ Wc2,
                          const float* __restrict__ bs0, const float* __restrict__ bs1,
                          const float* __restrict__ bs2,
                          const float* __restrict__ bc0, const float* __restrict__ bc1,
                          const float* __restrict__ bc2)
{
    __shared__ float red[1024];
    int tid = threadIdx.x;
    int a = blockIdx.x * 256 + (tid & 255);
    int part = tid >> 8;                 // 0..3
    int t = blockIdx.y;
    const float* ctx = (t == 0) ? ctx0 : (t == 1) ? ctx1 : ctx2;
    const float* W   = (t == 0) ? Wc0  : (t == 1) ? Wc1  : Wc2;
    float acc = 0.f;
    int e0 = part * 192;
#pragma unroll 8
    for (int e = 0; e < 192; e++)
        acc += __ldg(ctx + e0 + e) * __ldg(W + (size_t)(e0 + e) * AA + a);
    red[tid] = acc;
    __syncthreads();
    if (tid < 256) {
        const float* bs = (t == 0) ? bs0 : (t == 1) ? bs1 : bs2;
        const float* bc = (t == 0) ? bc0 : (t == 1) ? bc1 : bc2;
        float r = bs[a] + bc[a] + red[tid] + red[256 + tid] + red[512 + tid] + red[768 + tid];
        g_cb[t * AA + a] = r;
    }
}

// ---------------- GEMM via mma.sync bf16 + tanh.v epilogue ----------------
// CTA 128x128, 8 warps (2x4), warp tile 64x32, BK=64 (2 chunks/stage),
// 3-stage cp.async with ONE barrier per iter, 2 CTAs/SM.
__global__ __launch_bounds__(256, 2) void gemm_e_mma(
    const float* __restrict__ v0, const float* __restrict__ v1, const float* __restrict__ v2,
    const int* __restrict__ lenp)
{
    extern __shared__ char smem[];   // 3 stages x 32KB + red 2KB
    int len = *lenp; if (len > S) len = S;
    int mt_blk = blockIdx.y;
    int m0 = mt_blk << 7;
    if (m0 >= len) return;
    int head = blockIdx.x >> 4, nt_blk = blockIdx.x & 15;

    int tid = threadIdx.x, l = tid & 31, wid = tid >> 5;
    int warp_m = wid >> 2, warp_n = wid & 3;
    uint32_t sb = smem_u32(smem);
    float* red = (float*)(smem + RED_OFF);

    const char* gA = g_Abf + (size_t)mt_blk * KST * 8192;
    const char* gB = g_Bbf + (size_t)(head * NT + nt_blk) * KST * 8192;

    float acc[4][4][4];
#pragma unroll
    for (int i = 0; i < 4; i++)
#pragma unroll
        for (int j = 0; j < 4; j++)
#pragma unroll
            for (int q = 0; q < 4; q++) acc[i][j][q] = 0.f;

    // chunk c in [0,96): A chunk = c<64 ? c : c-64 ; B chunk = c<32 ? c : c-32
    auto issue = [&](int j, int buf) {
        uint32_t st = sb + (uint32_t)buf * STG;
#pragma unroll
        for (int h = 0; h < 2; h++) {
            int c = 2 * j + h;
            int aIdx = (c < 64) ? c : (c - 64);
            int bIdx = (c < 32) ? c : (c - 32);
            const char* srcA = gA + (size_t)aIdx * 8192;
            const char* srcB = gB + (size_t)bIdx * 8192;
            uint32_t sA = st + (uint32_t)h * 8192;
            uint32_t sB = st + 16384 + (uint32_t)h * 8192;
#pragma unroll
            for (int t = 0; t < 2; t++)
                cp16(sA + (uint32_t)(tid + t * 256) * 16, srcA + (size_t)(tid + t * 256) * 16);
#pragma unroll
            for (int t = 0; t < 2; t++)
                cp16(sB + (uint32_t)(tid + t * 256) * 16, srcB + (size_t)(tid + t * 256) * 16);
        }
        cp_commit();
    };

    const int NITER = KTC / 2;   // 48
    issue(0, 0);
    issue(1, 1);
    int buf = 0;
    for (int j = 0; j < NITER; j++) {
        if (j + 1 < NITER) cp_wait1(); else cp_wait0();
        __syncthreads();           // stage j ready; all warps done reading stage (j-1)%3
        if (j + 2 < NITER) {
            int nb = buf + 2; if (nb >= 3) nb -= 3;
            issue(j + 2, nb);      // overwrites stage (j-1)%3 — safe after barrier
        }
        uint32_t stg = sb + (uint32_t)buf * STG;
        int noff = (warp_n & 1) * 32;
#pragma unroll
        for (int kc = 0; kc < 2; kc++) {
            uint32_t aBase = stg + (uint32_t)kc * 8192;
            uint32_t bBase = stg + 16384 + (uint32_t)kc * 8192 + (uint32_t)(warp_n >> 1) * 4096;
#pragma unroll
            for (int ks = 0; ks < 2; ks++) {
                uint32_t af[4][4];
#pragma unroll
                for (int mt = 0; mt < 4; mt++) {
                    uint32_t addr = aBase + sw64((uint32_t)((warp_m * 64 + mt * 16 + (l & 15)) * 64
                                                            + ks * 32 + (l >> 4) * 16));
                    ldsm4(af[mt], addr);
                }
                uint32_t bf[2][4];
#pragma unroll
                for (int g = 0; g < 2; g++) {
                    uint32_t addr = bBase + sw128((uint32_t)((ks * 16 + (l & 15)) * 128
                                                             + (noff + g * 16 + (l >> 4) * 8) * 2));
                    ldsm4t(bf[g], addr);
                }
#pragma unroll
                for (int mt = 0; mt < 4; mt++)
#pragma unroll
                    for (int g = 0; g < 2; g++) {
                        mma16816(acc[mt][2 * g],     af[mt], bf[g][0], bf[g][1]);
                        mma16816(acc[mt][2 * g + 1], af[mt], bf[g][2], bf[g][3]);
                    }
            }
        }
        buf++; if (buf == 3) buf = 0;
    }

    // epilogue: e_row = sum_n tanh(u + cb[n]) * v[n]   (red is its own region)
    const float* v  = (head == 0) ? v0 : (head == 1) ? v1 : v2;
    const float* cb = g_cb + head * AA;
    int nbase = nt_blk * 128 + warp_n * 32;

    float rs[8];
#pragma unroll
    for (int i = 0; i < 8; i++) rs[i] = 0.f;
#pragma unroll
    for (int j = 0; j < 4; j++) {
        int c = nbase + j * 8 + (l & 3) * 2;
        float cb0 = __ldg(cb + c), cb1 = __ldg(cb + c + 1);
        float vv0 = __ldg(v + c),  vv1 = __ldg(v + c + 1);
#pragma unroll
        for (int mt = 0; mt < 4; mt++) {
            const float* a = acc[mt][j];
            rs[mt * 2 + 0] += tanha(a[0] + cb0) * vv0 + tanha(a[1] + cb1) * vv1;
            rs[mt * 2 + 1] += tanha(a[2] + cb0) * vv0 + tanha(a[3] + cb1) * vv1;
        }
    }
#pragma unroll
    for (int i = 0; i < 8; i++) {
        rs[i] += __shfl_xor_sync(0xffffffffu, rs[i], 1);
        rs[i] += __shfl_xor_sync(0xffffffffu, rs[i], 2);
    }
    if ((l & 3) == 0) {
#pragma unroll
        for (int mt = 0; mt < 4; mt++)
#pragma unroll
            for (int h = 0; h < 2; h++) {
                int row = warp_m * 64 + mt * 16 + h * 8 + (l >> 2);
                red[row * 4 + warp_n] = rs[mt * 2 + h];
            }
    }
    __syncthreads();
    if (tid < 128) {
        float e = red[tid * 4] + red[tid * 4 + 1] + red[tid * 4 + 2] + red[tid * 4 + 3];
        g_epart[(size_t)(head * NT + nt_blk) * S + m0 + tid] = e;
    }
}

// ---------------- parallel reduce: efull[t][s] = sum_nt epart ---------------
__global__ void reduce_e_kernel()
{
    int idx = blockIdx.x * 256 + threadIdx.x;   // 0 .. 3*S
    int t = idx >> 13;
    int s = idx & (S - 1);
    float acc = 0.f;
#pragma unroll
    for (int nt = 0; nt < NT; nt++)
        acc += g_epart[(size_t)(t * NT + nt) * S + s];
    g_efull[idx] = acc;
}

// ---------------- masked softmax (3 heads) + mean, one block ----------------
__global__ void attn_weights_kernel(const float* __restrict__ bv0, const float* __restrict__ bv1,
                                    const float* __restrict__ bv2, const int* __restrict__ lenp)
{
    __shared__ float sm[1024];
    __shared__ float hm[3], hzi[3];
    int tid = threadIdx.x;
    int len = *lenp; if (len > S) len = S;
    if (len <= 0) {
#pragma unroll
        for (int i = 0; i < 8; i++) g_fused[tid + i * 1024] = 0.f;
        return;
    }
    const float NEGINF = __int_as_float(0xff800000);
    float vals[3][8];
#pragma unroll
    for (int t = 0; t < 3; t++) {
        float bv = (t == 0) ? *bv0 : (t == 1) ? *bv1 : *bv2;
#pragma unroll
        for (int i = 0; i < 8; i++) {
            int s = tid + i * 1024;
            vals[t][i] = (s < len) ? (bv + g_efull[t * S + s]) : NEGINF;
        }
    }
#pragma unroll
    for (int t = 0; t < 3; t++) {
        float mx = NEGINF;
#pragma unroll
        for (int i = 0; i < 8; i++) mx = fmaxf(mx, vals[t][i]);
        sm[tid] = mx; __syncthreads();
        for (int off = 512; off > 0; off >>= 1) {
            if (tid < off) sm[tid] = fmaxf(sm[tid], sm[tid + off]);
            __syncthreads();
        }
        float m = sm[0]; __syncthreads();
        float z = 0.f;
#pragma unroll
        for (int i = 0; i < 8; i++) z += expf(vals[t][i] - m);   // exp(-inf)=0
        sm[tid] = z; __syncthreads();
        for (int off = 512; off > 0; off >>= 1) {
            if (tid < off) sm[tid] += sm[tid + off];
            __syncthreads();
        }
        if (tid == 0) { hm[t] = m; hzi[t] = 1.f / sm[0]; }
        __syncthreads();
    }
#pragma unroll
    for (int i = 0; i < 8; i++) {
        int s = tid + i * 1024;
        float f = 0.f;
        if (s < len) {
#pragma unroll
            for (int t = 0; t < 3; t++)
                f += expf(vals[t][i] - hm[t]) * hzi[t];
            f *= (1.f / 3.f);
        }
        g_fused[s] = f;
    }
}

// ---------------- weighted sum over sentence (2D grid) ----------------------
__global__ void outpart_kernel(const float* __restrict__ sent, const int* __restrict__ lenp)
{
    int h = blockIdx.x * 256 + threadIdx.x;    // 4 x 256
    int c = blockIdx.y;                        // 128 chunks of 64 rows
    int len = *lenp; if (len > S) len = S;
    float acc = 0.f;
    int s0 = c * 64;
    int send = min(s0 + 64, len);
    for (int s = s0; s < send; s++)
        acc += g_fused[s] * sent[(size_t)s * H2 + h];
    g_outpart[c * H2 + h] = acc;
}

__global__ void final_kernel(float* __restrict__ out)
{
    int h = blockIdx.x * 256 + threadIdx.x;
    float acc = 0.f;
#pragma unroll
    for (int c = 0; c < NCHUNK; c++) acc += g_outpart[c * H2 + h];
    out[h] = acc;
}

// ---------------- launch ----------------
extern "C" void kernel_launch(void* const* d_in, const int* in_sizes, int n_in,
                              void* d_out, int out_size)
{
    const float* sent = (const float*)d_in[0];
    const int*   len  = (const int*)d_in[1];
    const float* pos  = (const float*)d_in[2];
    const float* card = (const float*)d_in[3];
    const float* hdl  = (const float*)d_in[4];

    const float* Ws_p = (const float*)d_in[5];
    const float* bs_p = (const float*)d_in[6];
    const float* Wc_p = (const float*)d_in[7];
    const float* bc_p = (const float*)d_in[8];
    const float* v_p  = (const float*)d_in[9];
    const float* bv_p = (const float*)d_in[10];

    const float* Ws_c = (const float*)d_in[11];
    const float* bs_c = (const float*)d_in[12];
    const float* Wc_c = (const float*)d_in[13];
    const float* bc_c = (const float*)d_in[14];
    const float* v_c  = (const float*)d_in[15];
    const float* bv_c = (const float*)d_in[16];

    const float* Ws_h = (const float*)d_in[17];
    const float* bs_h = (const float*)d_in[18];
    const float* Wc_h = (const float*)d_in[19];
    const float* bc_h = (const float*)d_in[20];
    const float* v_h  = (const float*)d_in[21];
    const float* bv_h = (const float*)d_in[22];

    float* out = (float*)d_out;

    cudaFuncSetAttribute(gemm_e_mma, cudaFuncAttributeMaxDynamicSharedMemorySize, GSMEM);

    convA_kernel<<<(S * H2) / 256, 256>>>(sent, len);
    convB_kernel<<<(3 * H2 * AA) / 256, 256>>>(Ws_p, Ws_c, Ws_h);
    cb_kernel<<<dim3(AA / 256, 3), 1024>>>(pos, card, hdl, Wc_p, Wc_c, Wc_h,
                                           bs_p, bs_c, bs_h, bc_p, bc_c, bc_h);
    gemm_e_mma<<<dim3(3 * NT, MT), 256, GSMEM>>>(v_p, v_c, v_h, len);
    reduce_e_kernel<<<(3 * S) / 256, 256>>>();
    attn_weights_kernel<<<1, 1024>>>(bv_p, bv_c, bv_h, len);
    outpart_kernel<<<dim3(4, NCHUNK), 256>>>(sent, len);
    final_kernel<<<H2 / 256, 256>>>(out);
}

// round 15
// speedup vs baseline: 1.4720x; 1.4720x over previous
#include <cuda_runtime.h>
#include <cuda_bf16.h>
#include <math.h>
#include <stdint.h>

#define S   8192
#define H2  1024
#define AA  2048
#define NT  16       // N-tiles of 128 per head
#define KTC 96       // K'-chunks of 32 (3-term folded K)
#define KST 64       // stored chunks per operand (hi|lo)
#define MT  64       // M-tiles of 128
#define NCHUNK 128   // output chunks of 64 rows
#define STG 32768    // bytes per pipeline stage (A 16KB + B 16KB)

// A tiles: [mt][64][128 rows][32 halves] (8KB/chunk, SW64 rows of 64B)  = 32MB
// B tiles: [head*16+nt][64][2 sub][32 k][64 n halves] (8KB/chunk, SW128) = 24MB
__device__ char  g_Abf[(size_t)MT * KST * 8192];
__device__ char  g_Bbf[(size_t)3 * NT * KST * 8192];
__device__ float g_cb[3 * AA];
__device__ float g_epart[(size_t)3 * NT * S];
__device__ float g_efull[3 * S];
__device__ float g_fused[S];
__device__ float g_outpart[NCHUNK * H2];

// ---------------- helpers ----------------
__device__ __forceinline__ uint32_t smem_u32(const void* p) {
    uint32_t a;
    asm("{ .reg .u64 t; cvta.to.shared.u64 t, %1; cvt.u32.u64 %0, t; }" : "=r"(a) : "l"(p));
    return a;
}
__device__ __forceinline__ uint32_t sw64(uint32_t x)  { return x ^ ((x >> 3) & 0x30); }
__device__ __forceinline__ uint32_t sw128(uint32_t x) { return x ^ ((x >> 3) & 0x70); }

__device__ __forceinline__ void cp16(uint32_t saddr, const void* gaddr) {
    asm volatile("cp.async.cg.shared.global [%0], [%1], 16;" :: "r"(saddr), "l"(gaddr));
}
__device__ __forceinline__ void cp_commit() { asm volatile("cp.async.commit_group;"); }
__device__ __forceinline__ void cp_wait1()  { asm volatile("cp.async.wait_group 1;"); }
__device__ __forceinline__ void cp_wait0()  { asm volatile("cp.async.wait_group 0;"); }

__device__ __forceinline__ void ldsm4(uint32_t* r, uint32_t addr) {
    asm volatile("ldmatrix.sync.aligned.m8n8.x4.shared.b16 {%0,%1,%2,%3}, [%4];"
                 : "=r"(r[0]), "=r"(r[1]), "=r"(r[2]), "=r"(r[3]) : "r"(addr));
}
__device__ __forceinline__ void ldsm4t(uint32_t* r, uint32_t addr) {
    asm volatile("ldmatrix.sync.aligned.m8n8.x4.trans.shared.b16 {%0,%1,%2,%3}, [%4];"
                 : "=r"(r[0]), "=r"(r[1]), "=r"(r[2]), "=r"(r[3]) : "r"(addr));
}
__device__ __forceinline__ void mma16816(float* d, const uint32_t* a, uint32_t b0, uint32_t b1) {
    asm volatile(
        "mma.sync.aligned.m16n8k16.row.col.f32.bf16.bf16.f32 "
        "{%0,%1,%2,%3}, {%4,%5,%6,%7}, {%8,%9}, {%0,%1,%2,%3};"
        : "+f"(d[0]), "+f"(d[1]), "+f"(d[2]), "+f"(d[3])
        : "r"(a[0]), "r"(a[1]), "r"(a[2]), "r"(a[3]), "r"(b0), "r"(b1));
}
__device__ __forceinline__ float tanha(float x) {
    float y;
    asm("tanh.approx.f32 %0, %1;" : "=f"(y) : "f"(x));
    return y;
}

// ---------------- conv A: fp32 sentence -> bf16 hi|lo swizzled tiles ---------
__global__ void convA_kernel(const float* __restrict__ sent, const int* __restrict__ lenp)
{
    int len = *lenp; if (len > S) len = S;
    int mlim = (len + 127) & ~127;
    int idx = blockIdx.x * 256 + threadIdx.x;
    int m = idx >> 10;
    if (m >= mlim) return;
    int k = idx & 1023;
    float x = sent[idx];
    __nv_bfloat16 hi = __float2bfloat16(x);
    __nv_bfloat16 lo = __float2bfloat16(x - __bfloat162float(hi));
    int mt = m >> 7, r = m & 127, kc = k >> 5, c = k & 31;
    uint32_t off = sw64((uint32_t)(r * 64 + c * 2));
    char* base = g_Abf + (size_t)mt * KST * 8192;
    *(__nv_bfloat16*)(base + (size_t)kc * 8192 + off)        = hi;
    *(__nv_bfloat16*)(base + (size_t)(32 + kc) * 8192 + off) = lo;
}

// ---------------- conv B: W[k][n] -> bf16 hi|lo swizzled [k][n] tiles --------
__global__ void convB_kernel(const float* __restrict__ W0, const float* __restrict__ W1,
                             const float* __restrict__ W2)
{
    int idx = blockIdx.x * 256 + threadIdx.x;
    int head = idx >> 21;
    int rem = idx & ((1 << 21) - 1);
    int k = rem >> 11, n = rem & 2047;
    const float* W = (head == 0) ? W0 : (head == 1) ? W1 : W2;
    float x = W[rem];
    __nv_bfloat16 hi = __float2bfloat16(x);
    __nv_bfloat16 lo = __float2bfloat16(x - __bfloat162float(hi));
    int nt = n >> 7, nloc = n & 127, sub = nloc >> 6, nc = nloc & 63;
    int kc = k >> 5, kr = k & 31;
    uint32_t off = (uint32_t)(sub * 4096) + sw128((uint32_t)(kr * 128 + nc * 2));
    char* base = g_Bbf + (size_t)(head * NT + nt) * KST * 8192;
    *(__nv_bfloat16*)(base + (size_t)kc * 8192 + off)        = hi;
    *(__nv_bfloat16*)(base + (size_t)(32 + kc) * 8192 + off) = lo;
}

// ---------------- context bias: cb = b_s + b_c + ctx @ W_c -------------------
__global__ void cb_kernel(const float* __restrict__ ctx0, const float* __restrict__ ctx1,
                          const float* __restrict__ ctx2,
                          const float* __restrict__ Wc0, const float* __restrict__ Wc1,
                          const float* __restrict__ Wc2,
                          const float* __restrict__ bs0, const float* __restrict__ bs1,
                          const float* __restrict__ bs2,
                          const float* __restrict__ bc0, const float* __restrict__ bc1,
                          const float* __restrict__ bc2)
{
    __shared__ float red[1024];
    int tid = threadIdx.x;
    int a = blockIdx.x * 256 + (tid & 255);
    int part = tid >> 8;                 // 0..3
    int t = blockIdx.y;
    const float* ctx = (t == 0) ? ctx0 : (t == 1) ? ctx1 : ctx2;
    const float* W   = (t == 0) ? Wc0  : (t == 1) ? Wc1  : Wc2;
    float acc = 0.f;
    int e0 = part * 192;
#pragma unroll 8
    for (int e = 0; e < 192; e++)
        acc += __ldg(ctx + e0 + e) * __ldg(W + (size_t)(e0 + e) * AA + a);
    red[tid] = acc;
    __syncthreads();
    if (tid < 256) {
        const float* bs = (t == 0) ? bs0 : (t == 1) ? bs1 : bs2;
        const float* bc = (t == 0) ? bc0 : (t == 1) ? bc1 : bc2;
        float r = bs[a] + bc[a] + red[tid] + red[256 + tid] + red[512 + tid] + red[768 + tid];
        g_cb[t * AA + a] = r;
    }
}

// ---------------- GEMM via mma.sync bf16 + tanh.v epilogue ----------------
// CTA 128x128, 8 warps (2x4), warp tile 64x32, BK=64 (2 chunks/stage),
// 2-stage cp.async (issue-before-wait, two barriers/iter), 2 CTAs/SM.
// R12 config — best measured (166 µs, tensor 71.7%). Do not change pipeline.
__global__ __launch_bounds__(256, 2) void gemm_e_mma(
    const float* __restrict__ v0, const float* __restrict__ v1, const float* __restrict__ v2,
    const int* __restrict__ lenp)
{
    extern __shared__ char smem[];   // 2 stages x 32KB
    int len = *lenp; if (len > S) len = S;
    int mt_blk = blockIdx.y;
    int m0 = mt_blk << 7;
    if (m0 >= len) return;
    int head = blockIdx.x >> 4, nt_blk = blockIdx.x & 15;

    int tid = threadIdx.x, l = tid & 31, wid = tid >> 5;
    int warp_m = wid >> 2, warp_n = wid & 3;
    uint32_t sb = smem_u32(smem);

    const char* gA = g_Abf + (size_t)mt_blk * KST * 8192;
    const char* gB = g_Bbf + (size_t)(head * NT + nt_blk) * KST * 8192;

    float acc[4][4][4];
#pragma unroll
    for (int i = 0; i < 4; i++)
#pragma unroll
        for (int j = 0; j < 4; j++)
#pragma unroll
            for (int q = 0; q < 4; q++) acc[i][j][q] = 0.f;

    // chunk c in [0,96): A chunk = c<64 ? c : c-64 ; B chunk = c<32 ? c : c-32
    auto issue = [&](int j, int buf) {
        uint32_t st = sb + (uint32_t)buf * STG;
#pragma unroll
        for (int h = 0; h < 2; h++) {
            int c = 2 * j + h;
            int aIdx = (c < 64) ? c : (c - 64);
            int bIdx = (c < 32) ? c : (c - 32);
            const char* srcA = gA + (size_t)aIdx * 8192;
            const char* srcB = gB + (size_t)bIdx * 8192;
            uint32_t sA = st + (uint32_t)h * 8192;
            uint32_t sB = st + 16384 + (uint32_t)h * 8192;
#pragma unroll
            for (int t = 0; t < 2; t++)
                cp16(sA + (uint32_t)(tid + t * 256) * 16, srcA + (size_t)(tid + t * 256) * 16);
#pragma unroll
            for (int t = 0; t < 2; t++)
                cp16(sB + (uint32_t)(tid + t * 256) * 16, srcB + (size_t)(tid + t * 256) * 16);
        }
        cp_commit();
    };

    const int NITER = KTC / 2;   // 48
    issue(0, 0);
    for (int j = 0; j < NITER; j++) {
        if (j + 1 < NITER) { issue(j + 1, (j + 1) & 1); cp_wait1(); }
        else               { cp_wait0(); }
        __syncthreads();

        uint32_t stg = sb + (uint32_t)(j & 1) * STG;
        int noff = (warp_n & 1) * 32;
#pragma unroll
        for (int kc = 0; kc < 2; kc++) {
            uint32_t aBase = stg + (uint32_t)kc * 8192;
            uint32_t bBase = stg + 16384 + (uint32_t)kc * 8192 + (uint32_t)(warp_n >> 1) * 4096;
#pragma unroll
            for (int ks = 0; ks < 2; ks++) {
                uint32_t af[4][4];
#pragma unroll
                for (int mt = 0; mt < 4; mt++) {
                    uint32_t addr = aBase + sw64((uint32_t)((warp_m * 64 + mt * 16 + (l & 15)) * 64
                                                            + ks * 32 + (l >> 4) * 16));
                    ldsm4(af[mt], addr);
                }
                uint32_t bf[2][4];
#pragma unroll
                for (int g = 0; g < 2; g++) {
                    uint32_t addr = bBase + sw128((uint32_t)((ks * 16 + (l & 15)) * 128
                                                             + (noff + g * 16 + (l >> 4) * 8) * 2));
                    ldsm4t(bf[g], addr);
                }
#pragma unroll
                for (int mt = 0; mt < 4; mt++)
#pragma unroll
                    for (int g = 0; g < 2; g++) {
                        mma16816(acc[mt][2 * g],     af[mt], bf[g][0], bf[g][1]);
                        mma16816(acc[mt][2 * g + 1], af[mt], bf[g][2], bf[g][3]);
                    }
            }
        }
        __syncthreads();
    }

    // epilogue: e_row = sum_n tanh(u + cb[n]) * v[n]
    const float* v  = (head == 0) ? v0 : (head == 1) ? v1 : v2;
    const float* cb = g_cb + head * AA;
    int nbase = nt_blk * 128 + warp_n * 32;

    float rs[8];
#pragma unroll
    for (int i = 0; i < 8; i++) rs[i] = 0.f;
#pragma unroll
    for (int j = 0; j < 4; j++) {
        int c = nbase + j * 8 + (l & 3) * 2;
        float cb0 = __ldg(cb + c), cb1 = __ldg(cb + c + 1);
        float vv0 = __ldg(v + c),  vv1 = __ldg(v + c + 1);
#pragma unroll
        for (int mt = 0; mt < 4; mt++) {
            const float* a = acc[mt][j];
            rs[mt * 2 + 0] += tanha(a[0] + cb0) * vv0 + tanha(a[1] + cb1) * vv1;
            rs[mt * 2 + 1] += tanha(a[2] + cb0) * vv0 + tanha(a[3] + cb1) * vv1;
        }
    }
#pragma unroll
    for (int i = 0; i < 8; i++) {
        rs[i] += __shfl_xor_sync(0xffffffffu, rs[i], 1);
        rs[i] += __shfl_xor_sync(0xffffffffu, rs[i], 2);
    }
    float* red = (float*)smem;      // mainloop done (barrier above) — safe alias
    if ((l & 3) == 0) {
#pragma unroll
        for (int mt = 0; mt < 4; mt++)
#pragma unroll
            for (int h = 0; h < 2; h++) {
                int row = warp_m * 64 + mt * 16 + h * 8 + (l >> 2);
                red[row * 4 + warp_n] = rs[mt * 2 + h];
            }
    }
    __syncthreads();
    if (tid < 128) {
        float e = red[tid * 4] + red[tid * 4 + 1] + red[tid * 4 + 2] + red[tid * 4 + 3];
        g_epart[(size_t)(head * NT + nt_blk) * S + m0 + tid] = e;
    }
}

// ---------------- parallel reduce: efull[t][s] = sum_nt epart ---------------
__global__ void reduce_e_kernel()
{
    int idx = blockIdx.x * 256 + threadIdx.x;   // 0 .. 3*S
    int t = idx >> 13;
    int s = idx & (S - 1);
    float acc = 0.f;
#pragma unroll
    for (int nt = 0; nt < NT; nt++)
        acc += g_epart[(size_t)(t * NT + nt) * S + s];
    g_efull[idx] = acc;
}

// ---------------- masked softmax (3 heads) + mean, one block ----------------
__global__ void attn_weights_kernel(const float* __restrict__ bv0, const float* __restrict__ bv1,
                                    const float* __restrict__ bv2, const int* __restrict__ lenp)
{
    __shared__ float sm[1024];
    __shared__ float hm[3], hzi[3];
    int tid = threadIdx.x;
    int len = *lenp; if (len > S) len = S;
    if (len <= 0) {
#pragma unroll
        for (int i = 0; i < 8; i++) g_fused[tid + i * 1024] = 0.f;
        return;
    }
    const float NEGINF = __int_as_float(0xff800000);
    float vals[3][8];
#pragma unroll
    for (int t = 0; t < 3; t++) {
        float bv = (t == 0) ? *bv0 : (t == 1) ? *bv1 : *bv2;
#pragma unroll
        for (int i = 0; i < 8; i++) {
            int s = tid + i * 1024;
            vals[t][i] = (s < len) ? (bv + g_efull[t * S + s]) : NEGINF;
        }
    }
#pragma unroll
    for (int t = 0; t < 3; t++) {
        float mx = NEGINF;
#pragma unroll
        for (int i = 0; i < 8; i++) mx = fmaxf(mx, vals[t][i]);
        sm[tid] = mx; __syncthreads();
        for (int off = 512; off > 0; off >>= 1) {
            if (tid < off) sm[tid] = fmaxf(sm[tid], sm[tid + off]);
            __syncthreads();
        }
        float m = sm[0]; __syncthreads();
        float z = 0.f;
#pragma unroll
        for (int i = 0; i < 8; i++) z += expf(vals[t][i] - m);   // exp(-inf)=0
        sm[tid] = z; __syncthreads();
        for (int off = 512; off > 0; off >>= 1) {
            if (tid < off) sm[tid] += sm[tid + off];
            __syncthreads();
        }
        if (tid == 0) { hm[t] = m; hzi[t] = 1.f / sm[0]; }
        __syncthreads();
    }
#pragma unroll
    for (int i = 0; i < 8; i++) {
        int s = tid + i * 1024;
        float f = 0.f;
        if (s < len) {
#pragma unroll
            for (int t = 0; t < 3; t++)
                f += expf(vals[t][i] - hm[t]) * hzi[t];
            f *= (1.f / 3.f);
        }
        g_fused[s] = f;
    }
}

// ---------------- weighted sum over sentence (2D grid) ----------------------
__global__ void outpart_kernel(const float* __restrict__ sent, const int* __restrict__ lenp)
{
    int h = blockIdx.x * 256 + threadIdx.x;    // 4 x 256
    int c = blockIdx.y;                        // 128 chunks of 64 rows
    int len = *lenp; if (len > S) len = S;
    float acc = 0.f;
    int s0 = c * 64;
    int send = min(s0 + 64, len);
    for (int s = s0; s < send; s++)
        acc += g_fused[s] * sent[(size_t)s * H2 + h];
    g_outpart[c * H2 + h] = acc;
}

__global__ void final_kernel(float* __restrict__ out)
{
    int h = blockIdx.x * 256 + threadIdx.x;
    float acc = 0.f;
#pragma unroll
    for (int c = 0; c < NCHUNK; c++) acc += g_outpart[c * H2 + h];
    out[h] = acc;
}

// ---------------- launch ----------------
extern "C" void kernel_launch(void* const* d_in, const int* in_sizes, int n_in,
                              void* d_out, int out_size)
{
    const float* sent = (const float*)d_in[0];
    const int*   len  = (const int*)d_in[1];
    const float* pos  = (const float*)d_in[2];
    const float* card = (const float*)d_in[3];
    const float* hdl  = (const float*)d_in[4];

    const float* Ws_p = (const float*)d_in[5];
    const float* bs_p = (const float*)d_in[6];
    const float* Wc_p = (const float*)d_in[7];
    const float* bc_p = (const float*)d_in[8];
    const float* v_p  = (const float*)d_in[9];
    const float* bv_p = (const float*)d_in[10];

    const float* Ws_c = (const float*)d_in[11];
    const float* bs_c = (const float*)d_in[12];
    const float* Wc_c = (const float*)d_in[13];
    const float* bc_c = (const float*)d_in[14];
    const float* v_c  = (const float*)d_in[15];
    const float* bv_c = (const float*)d_in[16];

    const float* Ws_h = (const float*)d_in[17];
    const float* bs_h = (const float*)d_in[18];
    const float* Wc_h = (const float*)d_in[19];
    const float* bc_h = (const float*)d_in[20];
    const float* v_h  = (const float*)d_in[21];
    const float* bv_h = (const float*)d_in[22];

    float* out = (float*)d_out;

    cudaFuncSetAttribute(gemm_e_mma, cudaFuncAttributeMaxDynamicSharedMemorySize, 2 * STG);

    convA_kernel<<<(S * H2) / 256, 256>>>(sent, len);
    convB_kernel<<<(3 * H2 * AA) / 256, 256>>>(Ws_p, Ws_c, Ws_h);
    cb_kernel<<<dim3(AA / 256, 3), 1024>>>(pos, card, hdl, Wc_p, Wc_c, Wc_h,
                                           bs_p, bs_c, bs_h, bc_p, bc_c, bc_h);
    gemm_e_mma<<<dim3(3 * NT, MT), 256, 2 * STG>>>(v_p, v_c, v_h, len);
    reduce_e_kernel<<<(3 * S) / 256, 256>>>();
    attn_weights_kernel<<<1, 1024>>>(bv_p, bv_c, bv_h, len);
    outpart_kernel<<<dim3(4, NCHUNK), 256>>>(sent, len);
    final_kernel<<<H2 / 256, 256>>>(out);
}

// round 16
// speedup vs baseline: 1.6346x; 1.1104x over previous
#include <cuda_runtime.h>
#include <cuda_bf16.h>
#include <math.h>
#include <stdint.h>

#define S   8192
#define H2  1024
#define AA  2048
#define NT  16       // N-tiles of 128 per head
#define KTC 96       // K'-chunks of 32 (3-term folded K)
#define KST 64       // stored chunks per operand (hi|lo)
#define MT  64       // M-tiles of 128
#define NCHUNK 128   // output chunks of 64 rows
#define STG 32768    // bytes per pipeline stage (A 16KB + B 16KB)

// A tiles: [mt][64][128 rows][32 halves] (8KB/chunk, SW64 rows of 64B)  = 32MB
// B tiles: [head*16+nt][64][2 sub][32 k][64 n halves] (8KB/chunk, SW128) = 24MB
__device__ char  g_Abf[(size_t)MT * KST * 8192];
__device__ char  g_Bbf[(size_t)3 * NT * KST * 8192];
__device__ float g_cb[3 * AA];
__device__ float g_epart[(size_t)3 * NT * S];
__device__ float g_efull[3 * S];
__device__ float g_fused[S];
__device__ float g_outpart[NCHUNK * H2];

// ---------------- helpers ----------------
__device__ __forceinline__ uint32_t smem_u32(const void* p) {
    uint32_t a;
    asm("{ .reg .u64 t; cvta.to.shared.u64 t, %1; cvt.u32.u64 %0, t; }" : "=r"(a) : "l"(p));
    return a;
}
__device__ __forceinline__ uint32_t sw64(uint32_t x)  { return x ^ ((x >> 3) & 0x30); }
__device__ __forceinline__ uint32_t sw128(uint32_t x) { return x ^ ((x >> 3) & 0x70); }

__device__ __forceinline__ void cp16(uint32_t saddr, const void* gaddr) {
    asm volatile("cp.async.cg.shared.global [%0], [%1], 16;" :: "r"(saddr), "l"(gaddr));
}
__device__ __forceinline__ void cp_commit() { asm volatile("cp.async.commit_group;"); }
__device__ __forceinline__ void cp_wait1()  { asm volatile("cp.async.wait_group 1;"); }
__device__ __forceinline__ void cp_wait0()  { asm volatile("cp.async.wait_group 0;"); }

__device__ __forceinline__ void ldsm4(uint32_t* r, uint32_t addr) {
    asm volatile("ldmatrix.sync.aligned.m8n8.x4.shared.b16 {%0,%1,%2,%3}, [%4];"
                 : "=r"(r[0]), "=r"(r[1]), "=r"(r[2]), "=r"(r[3]) : "r"(addr));
}
__device__ __forceinline__ void ldsm4t(uint32_t* r, uint32_t addr) {
    asm volatile("ldmatrix.sync.aligned.m8n8.x4.trans.shared.b16 {%0,%1,%2,%3}, [%4];"
                 : "=r"(r[0]), "=r"(r[1]), "=r"(r[2]), "=r"(r[3]) : "r"(addr));
}
__device__ __forceinline__ void mma16816(float* d, const uint32_t* a, uint32_t b0, uint32_t b1) {
    asm volatile(
        "mma.sync.aligned.m16n8k16.row.col.f32.bf16.bf16.f32 "
        "{%0,%1,%2,%3}, {%4,%5,%6,%7}, {%8,%9}, {%0,%1,%2,%3};"
        : "+f"(d[0]), "+f"(d[1]), "+f"(d[2]), "+f"(d[3])
        : "r"(a[0]), "r"(a[1]), "r"(a[2]), "r"(a[3]), "r"(b0), "r"(b1));
}
__device__ __forceinline__ float tanha(float x) {
    float y;
    asm("tanh.approx.f32 %0, %1;" : "=f"(y) : "f"(x));
    return y;
}

// pack 2 floats -> hi bf16x2 (returned) and lo bf16x2 (out-param)
__device__ __forceinline__ uint32_t pack2(float a, float b, uint32_t& lop) {
    __nv_bfloat16 ha = __float2bfloat16(a), hb = __float2bfloat16(b);
    __nv_bfloat16 la = __float2bfloat16(a - __bfloat162float(ha));
    __nv_bfloat16 lb = __float2bfloat16(b - __bfloat162float(hb));
    lop = (uint32_t)__bfloat16_as_ushort(la) | ((uint32_t)__bfloat16_as_ushort(lb) << 16);
    return (uint32_t)__bfloat16_as_ushort(ha) | ((uint32_t)__bfloat16_as_ushort(hb) << 16);
}

// ---------------- conv A (8-wide): sentence -> bf16 hi|lo swizzled tiles -----
__global__ void convA_kernel(const float* __restrict__ sent, const int* __restrict__ lenp)
{
    int len = *lenp; if (len > S) len = S;
    int mlim = (len + 127) & ~127;
    int idx = blockIdx.x * 256 + threadIdx.x;    // S*H2/8 threads
    int m = idx >> 7;                            // 128 vec8 per row
    if (m >= mlim) return;
    int k8 = (idx & 127) << 3;
    const float4* src = (const float4*)(sent + (size_t)m * H2 + k8);
    float4 f0 = src[0], f1 = src[1];
    uint4 hi, lo;
    hi.x = pack2(f0.x, f0.y, lo.x);
    hi.y = pack2(f0.z, f0.w, lo.y);
    hi.z = pack2(f1.x, f1.y, lo.z);
    hi.w = pack2(f1.z, f1.w, lo.w);
    int mt = m >> 7, r = m & 127, kc = k8 >> 5, c = k8 & 31;
    uint32_t off = sw64((uint32_t)(r * 64 + c * 2));   // 16B-aligned block
    char* base = g_Abf + (size_t)mt * KST * 8192;
    *(uint4*)(base + (size_t)kc * 8192 + off)        = hi;
    *(uint4*)(base + (size_t)(32 + kc) * 8192 + off) = lo;
}

// ---------------- conv B (8-wide): W[k][n] -> bf16 hi|lo swizzled tiles ------
__global__ void convB_kernel(const float* __restrict__ W0, const float* __restrict__ W1,
                             const float* __restrict__ W2)
{
    int idx = blockIdx.x * 256 + threadIdx.x;    // 3*H2*AA/8 threads
    int head = idx >> 18;                        // H2*AA/8 = 2^18
    int rem = idx & 0x3FFFF;
    int k = rem >> 8;                            // AA/8 = 256 vec8 per k-row
    int n = (rem & 255) << 3;
    const float* W = (head == 0) ? W0 : (head == 1) ? W1 : W2;
    const float4* src = (const float4*)(W + (size_t)k * AA + n);
    float4 f0 = src[0], f1 = src[1];
    uint4 hi, lo;
    hi.x = pack2(f0.x, f0.y, lo.x);
    hi.y = pack2(f0.z, f0.w, lo.y);
    hi.z = pack2(f1.x, f1.y, lo.z);
    hi.w = pack2(f1.z, f1.w, lo.w);
    int nt = n >> 7, nloc = n & 127, sub = nloc >> 6, nc = nloc & 63;
    int kc = k >> 5, kr = k & 31;
    uint32_t off = (uint32_t)(sub * 4096) + sw128((uint32_t)(kr * 128 + nc * 2));
    char* base = g_Bbf + (size_t)(head * NT + nt) * KST * 8192;
    *(uint4*)(base + (size_t)kc * 8192 + off)        = hi;
    *(uint4*)(base + (size_t)(32 + kc) * 8192 + off) = lo;
}

// ---------------- context bias: cb = b_s + b_c + ctx @ W_c -------------------
__global__ void cb_kernel(const float* __restrict__ ctx0, const float* __restrict__ ctx1,
                          const float* __restrict__ ctx2,
                          const float* __restrict__ Wc0, const float* __restrict__ Wc1,
                          const float* __restrict__ Wc2,
                          const float* __restrict__ bs0, const float* __restrict__ bs1,
                          const float* __restrict__ bs2,
                          const float* __restrict__ bc0, const float* __restrict__ bc1,
                          const float* __restrict__ bc2)
{
    __shared__ float red[1024];
    int tid = threadIdx.x;
    int a = blockIdx.x * 256 + (tid & 255);
    int part = tid >> 8;                 // 0..3
    int t = blockIdx.y;
    const float* ctx = (t == 0) ? ctx0 : (t == 1) ? ctx1 : ctx2;
    const float* W   = (t == 0) ? Wc0  : (t == 1) ? Wc1  : Wc2;
    float acc = 0.f;
    int e0 = part * 192;
#pragma unroll 8
    for (int e = 0; e < 192; e++)
        acc += __ldg(ctx + e0 + e) * __ldg(W + (size_t)(e0 + e) * AA + a);
    red[tid] = acc;
    __syncthreads();
    if (tid < 256) {
        const float* bs = (t == 0) ? bs0 : (t == 1) ? bs1 : bs2;
        const float* bc = (t == 0) ? bc0 : (t == 1) ? bc1 : bc2;
        float r = bs[a] + bc[a] + red[tid] + red[256 + tid] + red[512 + tid] + red[768 + tid];
        g_cb[t * AA + a] = r;
    }
}

// ---------------- GEMM via mma.sync bf16 + tanh.v epilogue ----------------
// CTA 128x128, 8 warps (2x4), warp tile 64x32, BK=64 (2 chunks/stage),
// 2-stage cp.async (issue-before-wait, two barriers/iter), 2 CTAs/SM.
// R12 config — best measured (166 µs, tensor 71.7%). Do not change pipeline.
__global__ __launch_bounds__(256, 2) void gemm_e_mma(
    const float* __restrict__ v0, const float* __restrict__ v1, const float* __restrict__ v2,
    const int* __restrict__ lenp)
{
    extern __shared__ char smem[];   // 2 stages x 32KB
    int len = *lenp; if (len > S) len = S;
    int mt_blk = blockIdx.y;
    int m0 = mt_blk << 7;
    if (m0 >= len) return;
    int head = blockIdx.x >> 4, nt_blk = blockIdx.x & 15;

    int tid = threadIdx.x, l = tid & 31, wid = tid >> 5;
    int warp_m = wid >> 2, warp_n = wid & 3;
    uint32_t sb = smem_u32(smem);

    const char* gA = g_Abf + (size_t)mt_blk * KST * 8192;
    const char* gB = g_Bbf + (size_t)(head * NT + nt_blk) * KST * 8192;

    float acc[4][4][4];
#pragma unroll
    for (int i = 0; i < 4; i++)
#pragma unroll
        for (int j = 0; j < 4; j++)
#pragma unroll
            for (int q = 0; q < 4; q++) acc[i][j][q] = 0.f;

    // chunk c in [0,96): A chunk = c<64 ? c : c-64 ; B chunk = c<32 ? c : c-32
    auto issue = [&](int j, int buf) {
        uint32_t st = sb + (uint32_t)buf * STG;
#pragma unroll
        for (int h = 0; h < 2; h++) {
            int c = 2 * j + h;
            int aIdx = (c < 64) ? c : (c - 64);
            int bIdx = (c < 32) ? c : (c - 32);
            const char* srcA = gA + (size_t)aIdx * 8192;
            const char* srcB = gB + (size_t)bIdx * 8192;
            uint32_t sA = st + (uint32_t)h * 8192;
            uint32_t sB = st + 16384 + (uint32_t)h * 8192;
#pragma unroll
            for (int t = 0; t < 2; t++)
                cp16(sA + (uint32_t)(tid + t * 256) * 16, srcA + (size_t)(tid + t * 256) * 16);
#pragma unroll
            for (int t = 0; t < 2; t++)
                cp16(sB + (uint32_t)(tid + t * 256) * 16, srcB + (size_t)(tid + t * 256) * 16);
        }
        cp_commit();
    };

    const int NITER = KTC / 2;   // 48
    issue(0, 0);
    for (int j = 0; j < NITER; j++) {
        if (j + 1 < NITER) { issue(j + 1, (j + 1) & 1); cp_wait1(); }
        else               { cp_wait0(); }
        __syncthreads();

        uint32_t stg = sb + (uint32_t)(j & 1) * STG;
        int noff = (warp_n & 1) * 32;
#pragma unroll
        for (int kc = 0; kc < 2; kc++) {
            uint32_t aBase = stg + (uint32_t)kc * 8192;
            uint32_t bBase = stg + 16384 + (uint32_t)kc * 8192 + (uint32_t)(warp_n >> 1) * 4096;
#pragma unroll
            for (int ks = 0; ks < 2; ks++) {
                uint32_t af[4][4];
#pragma unroll
                for (int mt = 0; mt < 4; mt++) {
                    uint32_t addr = aBase + sw64((uint32_t)((warp_m * 64 + mt * 16 + (l & 15)) * 64
                                                            + ks * 32 + (l >> 4) * 16));
                    ldsm4(af[mt], addr);
                }
                uint32_t bf[2][4];
#pragma unroll
                for (int g = 0; g < 2; g++) {
                    uint32_t addr = bBase + sw128((uint32_t)((ks * 16 + (l & 15)) * 128
                                                             + (noff + g * 16 + (l >> 4) * 8) * 2));
                    ldsm4t(bf[g], addr);
                }
#pragma unroll
                for (int mt = 0; mt < 4; mt++)
#pragma unroll
                    for (int g = 0; g < 2; g++) {
                        mma16816(acc[mt][2 * g],     af[mt], bf[g][0], bf[g][1]);
                        mma16816(acc[mt][2 * g + 1], af[mt], bf[g][2], bf[g][3]);
                    }
            }
        }
        __syncthreads();
    }

    // epilogue: e_row = sum_n tanh(u + cb[n]) * v[n]
    const float* v  = (head == 0) ? v0 : (head == 1) ? v1 : v2;
    const float* cb = g_cb + head * AA;
    int nbase = nt_blk * 128 + warp_n * 32;

    float rs[8];
#pragma unroll
    for (int i = 0; i < 8; i++) rs[i] = 0.f;
#pragma unroll
    for (int j = 0; j < 4; j++) {
        int c = nbase + j * 8 + (l & 3) * 2;
        float cb0 = __ldg(cb + c), cb1 = __ldg(cb + c + 1);
        float vv0 = __ldg(v + c),  vv1 = __ldg(v + c + 1);
#pragma unroll
        for (int mt = 0; mt < 4; mt++) {
            const float* a = acc[mt][j];
            rs[mt * 2 + 0] += tanha(a[0] + cb0) * vv0 + tanha(a[1] + cb1) * vv1;
            rs[mt * 2 + 1] += tanha(a[2] + cb0) * vv0 + tanha(a[3] + cb1) * vv1;
        }
    }
#pragma unroll
    for (int i = 0; i < 8; i++) {
        rs[i] += __shfl_xor_sync(0xffffffffu, rs[i], 1);
        rs[i] += __shfl_xor_sync(0xffffffffu, rs[i], 2);
    }
    float* red = (float*)smem;      // mainloop done (barrier above) — safe alias
    if ((l & 3) == 0) {
#pragma unroll
        for (int mt = 0; mt < 4; mt++)
#pragma unroll
            for (int h = 0; h < 2; h++) {
                int row = warp_m * 64 + mt * 16 + h * 8 + (l >> 2);
                red[row * 4 + warp_n] = rs[mt * 2 + h];
            }
    }
    __syncthreads();
    if (tid < 128) {
        float e = red[tid * 4] + red[tid * 4 + 1] + red[tid * 4 + 2] + red[tid * 4 + 3];
        g_epart[(size_t)(head * NT + nt_blk) * S + m0 + tid] = e;
    }
}

// ---------------- parallel reduce: efull[t][s] = sum_nt epart ---------------
__global__ void reduce_e_kernel()
{
    int idx = blockIdx.x * 256 + threadIdx.x;   // 0 .. 3*S
    int t = idx >> 13;
    int s = idx & (S - 1);
    float acc = 0.f;
#pragma unroll
    for (int nt = 0; nt < NT; nt++)
        acc += g_epart[(size_t)(t * NT + nt) * S + s];
    g_efull[idx] = acc;
}

// ---------------- masked softmax (3 heads) + mean, one block ----------------
__global__ void attn_weights_kernel(const float* __restrict__ bv0, const float* __restrict__ bv1,
                                    const float* __restrict__ bv2, const int* __restrict__ lenp)
{
    __shared__ float sm[1024];
    __shared__ float hm[3], hzi[3];
    int tid = threadIdx.x;
    int len = *lenp; if (len > S) len = S;
    if (len <= 0) {
#pragma unroll
        for (int i = 0; i < 8; i++) g_fused[tid + i * 1024] = 0.f;
        return;
    }
    const float NEGINF = __int_as_float(0xff800000);
    float vals[3][8];
#pragma unroll
    for (int t = 0; t < 3; t++) {
        float bv = (t == 0) ? *bv0 : (t == 1) ? *bv1 : *bv2;
#pragma unroll
        for (int i = 0; i < 8; i++) {
            int s = tid + i * 1024;
            vals[t][i] = (s < len) ? (bv + g_efull[t * S + s]) : NEGINF;
        }
    }
#pragma unroll
    for (int t = 0; t < 3; t++) {
        float mx = NEGINF;
#pragma unroll
        for (int i = 0; i < 8; i++) mx = fmaxf(mx, vals[t][i]);
        sm[tid] = mx; __syncthreads();
        for (int off = 512; off > 0; off >>= 1) {
            if (tid < off) sm[tid] = fmaxf(sm[tid], sm[tid + off]);
            __syncthreads();
        }
        float m = sm[0]; __syncthreads();
        float z = 0.f;
#pragma unroll
        for (int i = 0; i < 8; i++) z += expf(vals[t][i] - m);   // exp(-inf)=0
        sm[tid] = z; __syncthreads();
        for (int off = 512; off > 0; off >>= 1) {
            if (tid < off) sm[tid] += sm[tid + off];
            __syncthreads();
        }
        if (tid == 0) { hm[t] = m; hzi[t] = 1.f / sm[0]; }
        __syncthreads();
    }
#pragma unroll
    for (int i = 0; i < 8; i++) {
        int s = tid + i * 1024;
        float f = 0.f;
        if (s < len) {
#pragma unroll
            for (int t = 0; t < 3; t++)
                f += expf(vals[t][i] - hm[t]) * hzi[t];
            f *= (1.f / 3.f);
        }
        g_fused[s] = f;
    }
}

// ---------------- weighted sum over sentence (2D grid) ----------------------
__global__ void outpart_kernel(const float* __restrict__ sent, const int* __restrict__ lenp)
{
    int h = blockIdx.x * 256 + threadIdx.x;    // 4 x 256
    int c = blockIdx.y;                        // 128 chunks of 64 rows
    int len = *lenp; if (len > S) len = S;
    float acc = 0.f;
    int s0 = c * 64;
    int send = min(s0 + 64, len);
    for (int s = s0; s < send; s++)
        acc += g_fused[s] * sent[(size_t)s * H2 + h];
    g_outpart[c * H2 + h] = acc;
}

__global__ void final_kernel(float* __restrict__ out)
{
    int h = blockIdx.x * 256 + threadIdx.x;
    float acc = 0.f;
#pragma unroll
    for (int c = 0; c < NCHUNK; c++) acc += g_outpart[c * H2 + h];
    out[h] = acc;
}

// ---------------- launch ----------------
extern "C" void kernel_launch(void* const* d_in, const int* in_sizes, int n_in,
                              void* d_out, int out_size)
{
    const float* sent = (const float*)d_in[0];
    const int*   len  = (const int*)d_in[1];
    const float* pos  = (const float*)d_in[2];
    const float* card = (const float*)d_in[3];
    const float* hdl  = (const float*)d_in[4];

    const float* Ws_p = (const float*)d_in[5];
    const float* bs_p = (const float*)d_in[6];
    const float* Wc_p = (const float*)d_in[7];
    const float* bc_p = (const float*)d_in[8];
    const float* v_p  = (const float*)d_in[9];
    const float* bv_p = (const float*)d_in[10];

    const float* Ws_c = (const float*)d_in[11];
    const float* bs_c = (const float*)d_in[12];
    const float* Wc_c = (const float*)d_in[13];
    const float* bc_c = (const float*)d_in[14];
    const float* v_c  = (const float*)d_in[15];
    const float* bv_c = (const float*)d_in[16];

    const float* Ws_h = (const float*)d_in[17];
    const float* bs_h = (const float*)d_in[18];
    const float* Wc_h = (const float*)d_in[19];
    const float* bc_h = (const float*)d_in[20];
    const float* v_h  = (const float*)d_in[21];
    const float* bv_h = (const float*)d_in[22];

    float* out = (float*)d_out;

    cudaFuncSetAttribute(gemm_e_mma, cudaFuncAttributeMaxDynamicSharedMemorySize, 2 * STG);

    convA_kernel<<<(S * H2 / 8) / 256, 256>>>(sent, len);
    convB_kernel<<<(3 * H2 * AA / 8) / 256, 256>>>(Ws_p, Ws_c, Ws_h);
    cb_kernel<<<dim3(AA / 256, 3), 1024>>>(pos, card, hdl, Wc_p, Wc_c, Wc_h,
                                           bs_p, bs_c, bs_h, bc_p, bc_c, bc_h);
    gemm_e_mma<<<dim3(3 * NT, MT), 256, 2 * STG>>>(v_p, v_c, v_h, len);
    reduce_e_kernel<<<(3 * S) / 256, 256>>>();
    attn_weights_kernel<<<1, 1024>>>(bv_p, bv_c, bv_h, len);
    outpart_kernel<<<dim3(4, NCHUNK), 256>>>(sent, len);
    final_kernel<<<H2 / 256, 256>>>(out);
}

// round 17
// speedup vs baseline: 2.2688x; 1.3880x over previous
#include <cuda_runtime.h>
#include <cuda_fp16.h>
#include <math.h>
#include <stdint.h>

#define S   8192
#define H2  1024
#define AA  2048
#define NT  16       // N-tiles of 128 per head
#define KTC 64       // K'-chunks of 32 (fp16 2-term folded K: K'=2048)
#define KST 64       // stored A chunks (ha|la)
#define KSB 32       // stored B chunks (hb only)
#define MT  64       // M-tiles of 128
#define NCHUNK 128   // output chunks of 64 rows
#define STG 32768    // bytes per pipeline stage (A 16KB + B 16KB)

// A tiles: [mt][64][128 rows][32 halves] (8KB/chunk, SW64 rows of 64B)  = 32MB
// B tiles: [head*16+nt][32][2 sub][32 k][64 n halves] (8KB/chunk, SW128) = 12MB
__device__ char  g_Abf[(size_t)MT * KST * 8192];
__device__ char  g_Bbf[(size_t)3 * NT * KSB * 8192];
__device__ float g_cb[3 * AA];
__device__ float g_epart[(size_t)3 * NT * S];
__device__ float g_efull[3 * S];
__device__ float g_fused[S];
__device__ float g_outpart[NCHUNK * H2];

// ---------------- helpers ----------------
__device__ __forceinline__ uint32_t smem_u32(const void* p) {
    uint32_t a;
    asm("{ .reg .u64 t; cvta.to.shared.u64 t, %1; cvt.u32.u64 %0, t; }" : "=r"(a) : "l"(p));
    return a;
}
__device__ __forceinline__ uint32_t sw64(uint32_t x)  { return x ^ ((x >> 3) & 0x30); }
__device__ __forceinline__ uint32_t sw128(uint32_t x) { return x ^ ((x >> 3) & 0x70); }

__device__ __forceinline__ void cp16(uint32_t saddr, const void* gaddr) {
    asm volatile("cp.async.cg.shared.global [%0], [%1], 16;" :: "r"(saddr), "l"(gaddr));
}
__device__ __forceinline__ void cp_commit() { asm volatile("cp.async.commit_group;"); }
__device__ __forceinline__ void cp_wait1()  { asm volatile("cp.async.wait_group 1;"); }
__device__ __forceinline__ void cp_wait0()  { asm volatile("cp.async.wait_group 0;"); }

__device__ __forceinline__ void ldsm4(uint32_t* r, uint32_t addr) {
    asm volatile("ldmatrix.sync.aligned.m8n8.x4.shared.b16 {%0,%1,%2,%3}, [%4];"
                 : "=r"(r[0]), "=r"(r[1]), "=r"(r[2]), "=r"(r[3]) : "r"(addr));
}
__device__ __forceinline__ void ldsm4t(uint32_t* r, uint32_t addr) {
    asm volatile("ldmatrix.sync.aligned.m8n8.x4.trans.shared.b16 {%0,%1,%2,%3}, [%4];"
                 : "=r"(r[0]), "=r"(r[1]), "=r"(r[2]), "=r"(r[3]) : "r"(addr));
}
__device__ __forceinline__ void mma16816(float* d, const uint32_t* a, uint32_t b0, uint32_t b1) {
    asm volatile(
        "mma.sync.aligned.m16n8k16.row.col.f32.f16.f16.f32 "
        "{%0,%1,%2,%3}, {%4,%5,%6,%7}, {%8,%9}, {%0,%1,%2,%3};"
        : "+f"(d[0]), "+f"(d[1]), "+f"(d[2]), "+f"(d[3])
        : "r"(a[0]), "r"(a[1]), "r"(a[2]), "r"(a[3]), "r"(b0), "r"(b1));
}
__device__ __forceinline__ float tanha(float x) {
    float y;
    asm("tanh.approx.f32 %0, %1;" : "=f"(y) : "f"(x));
    return y;
}

// pack 2 floats -> hi f16x2 (returned) and lo f16x2 (out-param)
__device__ __forceinline__ uint32_t pack2h(float a, float b, uint32_t& lop) {
    __half ha = __float2half_rn(a), hb = __float2half_rn(b);
    __half la = __float2half_rn(a - __half2float(ha));
    __half lb = __float2half_rn(b - __half2float(hb));
    lop = (uint32_t)__half_as_ushort(la) | ((uint32_t)__half_as_ushort(lb) << 16);
    return (uint32_t)__half_as_ushort(ha) | ((uint32_t)__half_as_ushort(hb) << 16);
}

// ---------------- conv A (8-wide): sentence -> f16 hi|lo swizzled tiles ------
__global__ void convA_kernel(const float* __restrict__ sent, const int* __restrict__ lenp)
{
    int len = *lenp; if (len > S) len = S;
    int mlim = (len + 127) & ~127;
    int idx = blockIdx.x * 256 + threadIdx.x;    // S*H2/8 threads
    int m = idx >> 7;                            // 128 vec8 per row
    if (m >= mlim) return;
    int k8 = (idx & 127) << 3;
    const float4* src = (const float4*)(sent + (size_t)m * H2 + k8);
    float4 f0 = src[0], f1 = src[1];
    uint4 hi, lo;
    hi.x = pack2h(f0.x, f0.y, lo.x);
    hi.y = pack2h(f0.z, f0.w, lo.y);
    hi.z = pack2h(f1.x, f1.y, lo.z);
    hi.w = pack2h(f1.z, f1.w, lo.w);
    int mt = m >> 7, r = m & 127, kc = k8 >> 5, c = k8 & 31;
    uint32_t off = sw64((uint32_t)(r * 64 + c * 2));   // 16B-aligned block
    char* base = g_Abf + (size_t)mt * KST * 8192;
    *(uint4*)(base + (size_t)kc * 8192 + off)        = hi;
    *(uint4*)(base + (size_t)(32 + kc) * 8192 + off) = lo;
}

// ---------------- conv B (8-wide): W[k][n] -> f16 hi swizzled tiles ----------
__global__ void convB_kernel(const float* __restrict__ W0, const float* __restrict__ W1,
                             const float* __restrict__ W2)
{
    int idx = blockIdx.x * 256 + threadIdx.x;    // 3*H2*AA/8 threads
    int head = idx >> 18;                        // H2*AA/8 = 2^18
    int rem = idx & 0x3FFFF;
    int k = rem >> 8;                            // AA/8 = 256 vec8 per k-row
    int n = (rem & 255) << 3;
    const float* W = (head == 0) ? W0 : (head == 1) ? W1 : W2;
    const float4* src = (const float4*)(W + (size_t)k * AA + n);
    float4 f0 = src[0], f1 = src[1];
    uint4 hi;
    __half2* h = (__half2*)&hi;
    h[0] = __floats2half2_rn(f0.x, f0.y);
    h[1] = __floats2half2_rn(f0.z, f0.w);
    h[2] = __floats2half2_rn(f1.x, f1.y);
    h[3] = __floats2half2_rn(f1.z, f1.w);
    int nt = n >> 7, nloc = n & 127, sub = nloc >> 6, nc = nloc & 63;
    int kc = k >> 5, kr = k & 31;
    uint32_t off = (uint32_t)(sub * 4096) + sw128((uint32_t)(kr * 128 + nc * 2));
    char* base = g_Bbf + (size_t)(head * NT + nt) * KSB * 8192;
    *(uint4*)(base + (size_t)kc * 8192 + off) = hi;
}

// ---------------- context bias: cb = b_s + b_c + ctx @ W_c -------------------
__global__ void cb_kernel(const float* __restrict__ ctx0, const float* __restrict__ ctx1,
                          const float* __restrict__ ctx2,
                          const float* __restrict__ Wc0, const float* __restrict__ Wc1,
                          const float* __restrict__ Wc2,
                          const float* __restrict__ bs0, const float* __restrict__ bs1,
                          const float* __restrict__ bs2,
                          const float* __restrict__ bc0, const float* __restrict__ bc1,
                          const float* __restrict__ bc2)
{
    __shared__ float red[1024];
    int tid = threadIdx.x;
    int a = blockIdx.x * 256 + (tid & 255);
    int part = tid >> 8;                 // 0..3
    int t = blockIdx.y;
    const float* ctx = (t == 0) ? ctx0 : (t == 1) ? ctx1 : ctx2;
    const float* W   = (t == 0) ? Wc0  : (t == 1) ? Wc1  : Wc2;
    float acc = 0.f;
    int e0 = part * 192;
#pragma unroll 8
    for (int e = 0; e < 192; e++)
        acc += __ldg(ctx + e0 + e) * __ldg(W + (size_t)(e0 + e) * AA + a);
    red[tid] = acc;
    __syncthreads();
    if (tid < 256) {
        const float* bs = (t == 0) ? bs0 : (t == 1) ? bs1 : bs2;
        const float* bc = (t == 0) ? bc0 : (t == 1) ? bc1 : bc2;
        float r = bs[a] + bc[a] + red[tid] + red[256 + tid] + red[512 + tid] + red[768 + tid];
        g_cb[t * AA + a] = r;
    }
}

// ---------------- GEMM via mma.sync f16 + tanh.v epilogue ----------------
// CTA 128x128, 8 warps (2x4), warp tile 64x32, BK=64 (2 chunks/stage),
// 2-stage cp.async (issue-before-wait, two barriers/iter), 2 CTAs/SM.
__global__ __launch_bounds__(256, 2) void gemm_e_mma(
    const float* __restrict__ v0, const float* __restrict__ v1, const float* __restrict__ v2,
    const int* __restrict__ lenp)
{
    extern __shared__ char smem[];   // 2 stages x 32KB
    int len = *lenp; if (len > S) len = S;
    int mt_blk = blockIdx.y;
    int m0 = mt_blk << 7;
    if (m0 >= len) return;
    int head = blockIdx.x >> 4, nt_blk = blockIdx.x & 15;

    int tid = threadIdx.x, l = tid & 31, wid = tid >> 5;
    int warp_m = wid >> 2, warp_n = wid & 3;
    uint32_t sb = smem_u32(smem);

    const char* gA = g_Abf + (size_t)mt_blk * KST * 8192;
    const char* gB = g_Bbf + (size_t)(head * NT + nt_blk) * KSB * 8192;

    float acc[4][4][4];
#pragma unroll
    for (int i = 0; i < 4; i++)
#pragma unroll
        for (int j = 0; j < 4; j++)
#pragma unroll
            for (int q = 0; q < 4; q++) acc[i][j][q] = 0.f;

    // chunk c in [0,64): A chunk = c (ha 0..31 | la 32..63); B chunk = c & 31
    auto issue = [&](int j, int buf) {
        uint32_t st = sb + (uint32_t)buf * STG;
#pragma unroll
        for (int h = 0; h < 2; h++) {
            int c = 2 * j + h;
            int aIdx = c;
            int bIdx = c & 31;
            const char* srcA = gA + (size_t)aIdx * 8192;
            const char* srcB = gB + (size_t)bIdx * 8192;
            uint32_t sA = st + (uint32_t)h * 8192;
            uint32_t sB = st + 16384 + (uint32_t)h * 8192;
#pragma unroll
            for (int t = 0; t < 2; t++)
                cp16(sA + (uint32_t)(tid + t * 256) * 16, srcA + (size_t)(tid + t * 256) * 16);
#pragma unroll
            for (int t = 0; t < 2; t++)
                cp16(sB + (uint32_t)(tid + t * 256) * 16, srcB + (size_t)(tid + t * 256) * 16);
        }
        cp_commit();
    };

    const int NITER = KTC / 2;   // 32
    issue(0, 0);
    for (int j = 0; j < NITER; j++) {
        if (j + 1 < NITER) { issue(j + 1, (j + 1) & 1); cp_wait1(); }
        else               { cp_wait0(); }
        __syncthreads();

        uint32_t stg = sb + (uint32_t)(j & 1) * STG;
        int noff = (warp_n & 1) * 32;
#pragma unroll
        for (int kc = 0; kc < 2; kc++) {
            uint32_t aBase = stg + (uint32_t)kc * 8192;
            uint32_t bBase = stg + 16384 + (uint32_t)kc * 8192 + (uint32_t)(warp_n >> 1) * 4096;
#pragma unroll
            for (int ks = 0; ks < 2; ks++) {
                uint32_t af[4][4];
#pragma unroll
                for (int mt = 0; mt < 4; mt++) {
                    uint32_t addr = aBase + sw64((uint32_t)((warp_m * 64 + mt * 16 + (l & 15)) * 64
                                                            + ks * 32 + (l >> 4) * 16));
                    ldsm4(af[mt], addr);
                }
                uint32_t bf[2][4];
#pragma unroll
                for (int g = 0; g < 2; g++) {
                    uint32_t addr = bBase + sw128((uint32_t)((ks * 16 + (l & 15)) * 128
                                                             + (noff + g * 16 + (l >> 4) * 8) * 2));
                    ldsm4t(bf[g], addr);
                }
#pragma unroll
                for (int mt = 0; mt < 4; mt++)
#pragma unroll
                    for (int g = 0; g < 2; g++) {
                        mma16816(acc[mt][2 * g],     af[mt], bf[g][0], bf[g][1]);
                        mma16816(acc[mt][2 * g + 1], af[mt], bf[g][2], bf[g][3]);
                    }
            }
        }
        __syncthreads();
    }

    // epilogue: e_row = sum_n tanh(u + cb[n]) * v[n]
    const float* v  = (head == 0) ? v0 : (head == 1) ? v1 : v2;
    const float* cb = g_cb + head * AA;
    int nbase = nt_blk * 128 + warp_n * 32;

    float rs[8];
#pragma unroll
    for (int i = 0; i < 8; i++) rs[i] = 0.f;
#pragma unroll
    for (int j = 0; j < 4; j++) {
        int c = nbase + j * 8 + (l & 3) * 2;
        float cb0 = __ldg(cb + c), cb1 = __ldg(cb + c + 1);
        float vv0 = __ldg(v + c),  vv1 = __ldg(v + c + 1);
#pragma unroll
        for (int mt = 0; mt < 4; mt++) {
            const float* a = acc[mt][j];
            rs[mt * 2 + 0] += tanha(a[0] + cb0) * vv0 + tanha(a[1] + cb1) * vv1;
            rs[mt * 2 + 1] += tanha(a[2] + cb0) * vv0 + tanha(a[3] + cb1) * vv1;
        }
    }
#pragma unroll
    for (int i = 0; i < 8; i++) {
        rs[i] += __shfl_xor_sync(0xffffffffu, rs[i], 1);
        rs[i] += __shfl_xor_sync(0xffffffffu, rs[i], 2);
    }
    float* red = (float*)smem;      // mainloop done (barrier above) — safe alias
    if ((l & 3) == 0) {
#pragma unroll
        for (int mt = 0; mt < 4; mt++)
#pragma unroll
            for (int h = 0; h < 2; h++) {
                int row = warp_m * 64 + mt * 16 + h * 8 + (l >> 2);
                red[row * 4 + warp_n] = rs[mt * 2 + h];
            }
    }
    __syncthreads();
    if (tid < 128) {
        float e = red[tid * 4] + red[tid * 4 + 1] + red[tid * 4 + 2] + red[tid * 4 + 3];
        g_epart[(size_t)(head * NT + nt_blk) * S + m0 + tid] = e;
    }
}

// ---------------- parallel reduce: efull[t][s] = sum_nt epart ---------------
__global__ void reduce_e_kernel()
{
    int idx = blockIdx.x * 256 + threadIdx.x;   // 0 .. 3*S
    int t = idx >> 13;
    int s = idx & (S - 1);
    float acc = 0.f;
#pragma unroll
    for (int nt = 0; nt < NT; nt++)
        acc += g_epart[(size_t)(t * NT + nt) * S + s];
    g_efull[idx] = acc;
}

// ---------------- masked softmax (3 heads) + mean, one block ----------------
__global__ void attn_weights_kernel(const float* __restrict__ bv0, const float* __restrict__ bv1,
                                    const float* __restrict__ bv2, const int* __restrict__ lenp)
{
    __shared__ float sm[1024];
    __shared__ float hm[3], hzi[3];
    int tid = threadIdx.x;
    int len = *lenp; if (len > S) len = S;
    if (len <= 0) {
#pragma unroll
        for (int i = 0; i < 8; i++) g_fused[tid + i * 1024] = 0.f;
        return;
    }
    const float NEGINF = __int_as_float(0xff800000);
    float vals[3][8];
#pragma unroll
    for (int t = 0; t < 3; t++) {
        float bv = (t == 0) ? *bv0 : (t == 1) ? *bv1 : *bv2;
#pragma unroll
        for (int i = 0; i < 8; i++) {
            int s = tid + i * 1024;
            vals[t][i] = (s < len) ? (bv + g_efull[t * S + s]) : NEGINF;
        }
    }
#pragma unroll
    for (int t = 0; t < 3; t++) {
        float mx = NEGINF;
#pragma unroll
        for (int i = 0; i < 8; i++) mx = fmaxf(mx, vals[t][i]);
        sm[tid] = mx; __syncthreads();
        for (int off = 512; off > 0; off >>= 1) {
            if (tid < off) sm[tid] = fmaxf(sm[tid], sm[tid + off]);
            __syncthreads();
        }
        float m = sm[0]; __syncthreads();
        float z = 0.f;
#pragma unroll
        for (int i = 0; i < 8; i++) z += expf(vals[t][i] - m);   // exp(-inf)=0
        sm[tid] = z; __syncthreads();
        for (int off = 512; off > 0; off >>= 1) {
            if (tid < off) sm[tid] += sm[tid + off];
            __syncthreads();
        }
        if (tid == 0) { hm[t] = m; hzi[t] = 1.f / sm[0]; }
        __syncthreads();
    }
#pragma unroll
    for (int i = 0; i < 8; i++) {
        int s = tid + i * 1024;
        float f = 0.f;
        if (s < len) {
#pragma unroll
            for (int t = 0; t < 3; t++)
                f += expf(vals[t][i] - hm[t]) * hzi[t];
            f *= (1.f / 3.f);
        }
        g_fused[s] = f;
    }
}

// ---------------- weighted sum over sentence (2D grid) ----------------------
__global__ void outpart_kernel(const float* __restrict__ sent, const int* __restrict__ lenp)
{
    int h = blockIdx.x * 256 + threadIdx.x;    // 4 x 256
    int c = blockIdx.y;                        // 128 chunks of 64 rows
    int len = *lenp; if (len > S) len = S;
    float acc = 0.f;
    int s0 = c * 64;
    int send = min(s0 + 64, len);
    for (int s = s0; s < send; s++)
        acc += g_fused[s] * sent[(size_t)s * H2 + h];
    g_outpart[c * H2 + h] = acc;
}

__global__ void final_kernel(float* __restrict__ out)
{
    int h = blockIdx.x * 256 + threadIdx.x;
    float acc = 0.f;
#pragma unroll
    for (int c = 0; c < NCHUNK; c++) acc += g_outpart[c * H2 + h];
    out[h] = acc;
}

// ---------------- launch ----------------
extern "C" void kernel_launch(void* const* d_in, const int* in_sizes, int n_in,
                              void* d_out, int out_size)
{
    const float* sent = (const float*)d_in[0];
    const int*   len  = (const int*)d_in[1];
    const float* pos  = (const float*)d_in[2];
    const float* card = (const float*)d_in[3];
    const float* hdl  = (const float*)d_in[4];

    const float* Ws_p = (const float*)d_in[5];
    const float* bs_p = (const float*)d_in[6];
    const float* Wc_p = (const float*)d_in[7];
    const float* bc_p = (const float*)d_in[8];
    const float* v_p  = (const float*)d_in[9];
    const float* bv_p = (const float*)d_in[10];

    const float* Ws_c = (const float*)d_in[11];
    const float* bs_c = (const float*)d_in[12];
    const float* Wc_c = (const float*)d_in[13];
    const float* bc_c = (const float*)d_in[14];
    const float* v_c  = (const float*)d_in[15];
    const float* bv_c = (const float*)d_in[16];

    const float* Ws_h = (const float*)d_in[17];
    const float* bs_h = (const float*)d_in[18];
    const float* Wc_h = (const float*)d_in[19];
    const float* bc_h = (const float*)d_in[20];
    const float* v_h  = (const float*)d_in[21];
    const float* bv_h = (const float*)d_in[22];

    float* out = (float*)d_out;

    cudaFuncSetAttribute(gemm_e_mma, cudaFuncAttributeMaxDynamicSharedMemorySize, 2 * STG);

    convA_kernel<<<(S * H2 / 8) / 256, 256>>>(sent, len);
    convB_kernel<<<(3 * H2 * AA / 8) / 256, 256>>>(Ws_p, Ws_c, Ws_h);
    cb_kernel<<<dim3(AA / 256, 3), 1024>>>(pos, card, hdl, Wc_p, Wc_c, Wc_h,
                                           bs_p, bs_c, bs_h, bc_p, bc_c, bc_h);
    gemm_e_mma<<<dim3(3 * NT, MT), 256, 2 * STG>>>(v_p, v_c, v_h, len);
    reduce_e_kernel<<<(3 * S) / 256, 256>>>();
    attn_weights_kernel<<<1, 1024>>>(bv_p, bv_c, bv_h, len);
    outpart_kernel<<<dim3(4, NCHUNK), 256>>>(sent, len);
    final_kernel<<<H2 / 256, 256>>>(out);
}